// round 15
// baseline (speedup 1.0000x reference)
#include <cuda_runtime.h>
#include <math.h>

#define BDIM 16
#define SDIM 2048
#define IDIM 1024
#define HDIM 1024
#define NBLK 128   // GRU blocks (within the fused kernel)
#define NGRID 152  // fused grid (all SMs)
#define NTILES 6144u   // gi tiles: 16 bands * 16 b * 24 n

// Scratch (static __device__ — runtime allocation is forbidden)
__device__ float g_gi[(size_t)BDIM * SDIM * 3 * HDIM];   // [B,S,3H]
__device__ float g_rnn[(size_t)BDIM * SDIM * HDIM];      // [B,S,H]
__device__ float g_hT[2 * HDIM * BDIM];                  // transposed h, double-buffered

// grid barrier state (R4-style, self-resetting across graph replays)
__device__ unsigned g_count = 0;
__device__ volatile unsigned g_gen = 0;

// gi producer-consumer state (reset each launch by reset kernel)
__device__ unsigned g_tile_ctr;
__device__ unsigned g_band_done[16];

// ---------------------------------------------------------------------------
// helpers
// ---------------------------------------------------------------------------
__device__ __forceinline__ unsigned long long dup2(float x) {
    unsigned long long r;
    asm("mov.b64 %0, {%1, %1};" : "=l"(r) : "f"(x));
    return r;
}
__device__ __forceinline__ float2 unpack2(unsigned long long v) {
    float2 f;
    asm("mov.b64 {%0, %1}, %2;" : "=f"(f.x), "=f"(f.y) : "l"(v));
    return f;
}
#define FMA2(d, a, b) asm("fma.rn.f32x2 %0, %1, %2, %0;" : "+l"(d) : "l"(a), "l"(b))
#define ADD2(d, a)    asm("add.rn.f32x2 %0, %0, %1;"     : "+l"(d) : "l"(a))
#define BARN(id) asm volatile("bar.sync %0, 256;" :: "r"(id) : "memory")

__device__ __forceinline__ unsigned ld_acq(const unsigned* p) {
    unsigned v;
    asm volatile("ld.acquire.gpu.global.b32 %0, [%1];" : "=r"(v) : "l"(p) : "memory");
    return v;
}

// ---------------------------------------------------------------------------
// standalone NT SGEMM (R12 exact) — used for the fc GEMM after the GRU
// ---------------------------------------------------------------------------
__global__ void __launch_bounds__(256, 2) sgemm_nt(
    const float* __restrict__ A, const float* __restrict__ W,
    const float* __restrict__ bias, float* __restrict__ C,
    int M, int N, int K)
{
    __shared__ float As[2][8][128];
    __shared__ float Bs[2][8][128];

    const int tid = threadIdx.x;
    const int bm = blockIdx.y * 128;
    const int bn = blockIdx.x * 128;
    const int tx = tid & 15;
    const int ty = tid >> 4;
    const int lr = tid >> 1;
    const int hf = tid & 1;

    const float* Ap = A + (size_t)(bm + lr) * K + hf * 4;
    const float* Wp = W + (size_t)(bn + lr) * K + hf * 4;

    unsigned long long acc[8][4];
#pragma unroll
    for (int i = 0; i < 8; i++)
#pragma unroll
        for (int j = 0; j < 4; j++) acc[i][j] = 0ull;

    {
        float4 a0 = *(const float4*)(Ap);
        float4 w0 = *(const float4*)(Wp);
        As[0][hf * 4 + 0][lr] = a0.x; As[0][hf * 4 + 1][lr] = a0.y;
        As[0][hf * 4 + 2][lr] = a0.z; As[0][hf * 4 + 3][lr] = a0.w;
        Bs[0][hf * 4 + 0][lr] = w0.x; Bs[0][hf * 4 + 1][lr] = w0.y;
        Bs[0][hf * 4 + 2][lr] = w0.z; Bs[0][hf * 4 + 3][lr] = w0.w;
    }
    __syncthreads();

    const int NS = K / 8;
    for (int s = 0; s < NS; s++) {
        float4 an, wn;
        const bool more = (s + 1 < NS);
        if (more) {
            an = *(const float4*)(Ap + (s + 1) * 8);
            wn = *(const float4*)(Wp + (s + 1) * 8);
        }
        const int b = s & 1;
#pragma unroll
        for (int k = 0; k < 8; k++) {
            float a8[8];
            *(float4*)&a8[0] = *(const float4*)&As[b][k][ty * 8];
            *(float4*)&a8[4] = *(const float4*)&As[b][k][ty * 8 + 4];
            unsigned long long bp[4];
            {
                ulonglong2 t0 = *(const ulonglong2*)&Bs[b][k][tx * 8];
                ulonglong2 t1 = *(const ulonglong2*)&Bs[b][k][tx * 8 + 4];
                bp[0] = t0.x; bp[1] = t0.y; bp[2] = t1.x; bp[3] = t1.y;
            }
            unsigned long long ad[8];
#pragma unroll
            for (int i = 0; i < 8; i++) ad[i] = dup2(a8[i]);
#pragma unroll
            for (int i = 0; i < 8; i++)
#pragma unroll
                for (int j = 0; j < 4; j++)
                    FMA2(acc[i][j], ad[i], bp[j]);
        }
        if (more) {
            const int nb = b ^ 1;
            As[nb][hf * 4 + 0][lr] = an.x; As[nb][hf * 4 + 1][lr] = an.y;
            As[nb][hf * 4 + 2][lr] = an.z; As[nb][hf * 4 + 3][lr] = an.w;
            Bs[nb][hf * 4 + 0][lr] = wn.x; Bs[nb][hf * 4 + 1][lr] = wn.y;
            Bs[nb][hf * 4 + 2][lr] = wn.z; Bs[nb][hf * 4 + 3][lr] = wn.w;
        }
        __syncthreads();
    }

#pragma unroll
    for (int i = 0; i < 8; i++) {
        size_t row = (size_t)(bm + ty * 8 + i);
#pragma unroll
        for (int j = 0; j < 4; j++) {
            float2 f = unpack2(acc[i][j]);
            int n = bn + tx * 8 + 2 * j;
            float2 v;
            v.x = f.x + bias[n];
            v.y = f.y + bias[n + 1];
            *(float2*)&C[row * N + n] = v;
        }
    }
}

// ---------------------------------------------------------------------------
// Fused kernel: gi-GEMM workers (threads 0-255 everywhere, + 256-511 in
// blocks >= 128) and the persistent GRU (threads 256-511, blocks 0-127).
// SMEM: [0, 4160): worker region A; [4160, 8320): worker region B;
//       [8320, ...): GRU (w_s 24576 + h_s 20480 + red 384 floats).
// ---------------------------------------------------------------------------
#define HROW 20
#define SM_W   (24 * 1024)
#define SM_H   (1024 * HROW)
#define SM_RED 192                       // ull entries
#define GEMM_REGION 4160                 // floats (As 2048 + Bs 2048 + hdr 64)
#define GRU_BASE (2 * GEMM_REGION)
#define SMEM_FLOATS (GRU_BASE + SM_W + SM_H + SM_RED * 2)

__global__ void reset_queue_kernel()
{
    if (threadIdx.x == 0) g_tile_ctr = 0u;
    if (threadIdx.x < 16) g_band_done[threadIdx.x] = 0u;
}

// gi worker: grab tiles in s-band-major order, compute, mark band progress.
__device__ void gi_worker(const float* __restrict__ x,
                          const float* __restrict__ w_ih,
                          const float* __restrict__ b_ih,
                          float* __restrict__ gi,
                          float* region, int barid, int tid)
{
    float* As = region;                  // [2][8][128]
    float* Bs = region + 2048;
    volatile unsigned* hdr = (volatile unsigned*)(region + 4096);

    const int tx = tid & 15;
    const int ty = tid >> 4;
    const int lr = tid >> 1;
    const int hf = tid & 1;

    for (;;) {
        if (tid == 0) hdr[0] = atomicAdd(&g_tile_ctr, 1u);
        BARN(barid);
        unsigned T = hdr[0];
        if (T >= NTILES) break;

        const int sb = (int)(T / 384u);
        const int loc = (int)(T % 384u);
        const int bb = loc / 24;
        const int nt = loc % 24;
        const int bm = (bb * 16 + sb) * 128;
        const int bn = nt * 128;

        const float* Ap = x + (size_t)(bm + lr) * IDIM + hf * 4;
        const float* Wp = w_ih + (size_t)(bn + lr) * IDIM + hf * 4;

        unsigned long long acc[8][4];
#pragma unroll
        for (int i = 0; i < 8; i++)
#pragma unroll
            for (int j = 0; j < 4; j++) acc[i][j] = 0ull;

        {
            float4 a0 = *(const float4*)(Ap);
            float4 w0 = *(const float4*)(Wp);
            As[(0 * 8 + hf * 4 + 0) * 128 + lr] = a0.x;
            As[(0 * 8 + hf * 4 + 1) * 128 + lr] = a0.y;
            As[(0 * 8 + hf * 4 + 2) * 128 + lr] = a0.z;
            As[(0 * 8 + hf * 4 + 3) * 128 + lr] = a0.w;
            Bs[(0 * 8 + hf * 4 + 0) * 128 + lr] = w0.x;
            Bs[(0 * 8 + hf * 4 + 1) * 128 + lr] = w0.y;
            Bs[(0 * 8 + hf * 4 + 2) * 128 + lr] = w0.z;
            Bs[(0 * 8 + hf * 4 + 3) * 128 + lr] = w0.w;
        }
        BARN(barid);

        const int NS = IDIM / 8;
        for (int s = 0; s < NS; s++) {
            float4 an, wn;
            const bool more = (s + 1 < NS);
            if (more) {
                an = *(const float4*)(Ap + (s + 1) * 8);
                wn = *(const float4*)(Wp + (s + 1) * 8);
            }
            const int bsel = s & 1;
            const float* Asb = As + bsel * 1024;
            const float* Bsb = Bs + bsel * 1024;
#pragma unroll
            for (int k = 0; k < 8; k++) {
                float a8[8];
                *(float4*)&a8[0] = *(const float4*)&Asb[k * 128 + ty * 8];
                *(float4*)&a8[4] = *(const float4*)&Asb[k * 128 + ty * 8 + 4];
                unsigned long long bp[4];
                {
                    ulonglong2 t0 = *(const ulonglong2*)&Bsb[k * 128 + tx * 8];
                    ulonglong2 t1 = *(const ulonglong2*)&Bsb[k * 128 + tx * 8 + 4];
                    bp[0] = t0.x; bp[1] = t0.y; bp[2] = t1.x; bp[3] = t1.y;
                }
                unsigned long long ad[8];
#pragma unroll
                for (int i = 0; i < 8; i++) ad[i] = dup2(a8[i]);
#pragma unroll
                for (int i = 0; i < 8; i++)
#pragma unroll
                    for (int j = 0; j < 4; j++)
                        FMA2(acc[i][j], ad[i], bp[j]);
            }
            if (more) {
                const int nb = bsel ^ 1;
                float* Asn = As + nb * 1024;
                float* Bsn = Bs + nb * 1024;
                Asn[(hf * 4 + 0) * 128 + lr] = an.x;
                Asn[(hf * 4 + 1) * 128 + lr] = an.y;
                Asn[(hf * 4 + 2) * 128 + lr] = an.z;
                Asn[(hf * 4 + 3) * 128 + lr] = an.w;
                Bsn[(hf * 4 + 0) * 128 + lr] = wn.x;
                Bsn[(hf * 4 + 1) * 128 + lr] = wn.y;
                Bsn[(hf * 4 + 2) * 128 + lr] = wn.z;
                Bsn[(hf * 4 + 3) * 128 + lr] = wn.w;
            }
            BARN(barid);
        }

#pragma unroll
        for (int i = 0; i < 8; i++) {
            size_t row = (size_t)(bm + ty * 8 + i);
#pragma unroll
            for (int j = 0; j < 4; j++) {
                float2 f = unpack2(acc[i][j]);
                int n = bn + tx * 8 + 2 * j;
                float2 v;
                v.x = f.x + b_ih[n];
                v.y = f.y + b_ih[n + 1];
                *(float2*)&gi[row * 3072 + n] = v;
            }
        }

        __threadfence();          // my stores -> L2
        BARN(barid);              // everyone's stores fenced
        if (tid == 0) atomicAdd(&g_band_done[sb], 1u);
    }
}

// GRU role (threads 256-511 of blocks 0-127). R12 math, named barrier 1.
__device__ void gru_role(const float* __restrict__ gi,
                         const float* __restrict__ w_hh,
                         const float* __restrict__ b_hh,
                         float* __restrict__ rnn,
                         float* __restrict__ hT,
                         float* sm, int tid /*0..255*/, int bx)
{
    float* w_s = sm + GRU_BASE;
    float* h_s = w_s + SM_W;
    unsigned long long* red_s = (unsigned long long*)(h_s + SM_H);

    const int cg = tid >> 6;
    const int ks = tid & 63;

    for (int idx = tid; idx < 24 * 256; idx += 256) {
        int lr = idx >> 8;
        int k4 = idx & 255;
        int g = lr >> 3, jl = lr & 7;
        float4 v = *(const float4*)(w_hh + ((size_t)(g * 1024 + bx * 8 + jl)) * 1024 + k4 * 4);
        *(float4*)(w_s + lr * 1024 + k4 * 4) = v;
    }

    const int jl_c = tid >> 4, b_c = tid & 15;
    const int col_c = bx * 8 + jl_c;
    float bh0 = 0.f, bh1 = 0.f, bh2 = 0.f;
    if (tid < 128) {
        bh0 = b_hh[col_c];
        bh1 = b_hh[1024 + col_c];
        bh2 = b_hh[2048 + col_c];
    }

    const int j0 = cg * 2;
    const float* wc[6];
#pragma unroll
    for (int jsub = 0; jsub < 2; jsub++)
#pragma unroll
        for (int g = 0; g < 3; g++)
            wc[jsub * 3 + g] = w_s + (g * 8 + j0 + jsub) * 1024 + ks;

    BARN(1);

    for (int t = 0; t < SDIM; t++) {
        // gate: gi band (t>>7) must be complete (384 tiles)
        if ((t & 127) == 0) {
            if (tid == 0) {
                const unsigned* bd = &g_band_done[t >> 7];
                while (ld_acq(bd) < 384u) {}
            }
            BARN(1);
        }

        // stage h_{t-1}
        if (t == 0) {
            float4 z4 = make_float4(0.f, 0.f, 0.f, 0.f);
            for (int r = tid; r < SM_H / 4; r += 256)
                ((float4*)h_s)[r] = z4;
        } else {
            const size_t hoff = (size_t)((t - 1) & 1) * (HDIM * BDIM);
            for (int r = tid; r < 4096; r += 256) {
                float4 v = *(const float4*)(hT + hoff + r * 4);
                int k = r >> 2, b4 = r & 3;
                *(float4*)(h_s + k * HROW + b4 * 4) = v;
            }
        }
        BARN(1);

        float gir = 0.f, giz = 0.f, gin = 0.f, hprev = 0.f;
        if (tid < 128) {
            const size_t gb = ((size_t)b_c * SDIM + t) * 3072 + col_c;
            gir = __ldg(gi + gb);
            giz = __ldg(gi + gb + 1024);
            gin = __ldg(gi + gb + 2048);
            hprev = h_s[col_c * HROW + b_c];
        }

        unsigned long long acc[6][8];
#pragma unroll
        for (int c = 0; c < 6; c++)
#pragma unroll
            for (int p = 0; p < 8; p++) acc[c][p] = 0ull;

#pragma unroll 4
        for (int i = 0; i < 16; i++) {
            const int k = ks + (i << 6);
            const float* hrow = h_s + k * HROW;
            unsigned long long hp[8];
            {
                ulonglong2 u0 = *(const ulonglong2*)(hrow);
                ulonglong2 u1 = *(const ulonglong2*)(hrow + 4);
                ulonglong2 u2 = *(const ulonglong2*)(hrow + 8);
                ulonglong2 u3 = *(const ulonglong2*)(hrow + 12);
                hp[0] = u0.x; hp[1] = u0.y; hp[2] = u1.x; hp[3] = u1.y;
                hp[4] = u2.x; hp[5] = u2.y; hp[6] = u3.x; hp[7] = u3.y;
            }
#pragma unroll
            for (int c = 0; c < 6; c++) {
                unsigned long long wd = dup2(wc[c][i << 6]);
#pragma unroll
                for (int p = 0; p < 8; p++) FMA2(acc[c][p], wd, hp[p]);
            }
        }

        unsigned long long* dmp = (unsigned long long*)h_s;
#pragma unroll
        for (int hh = 0; hh < 2; hh++) {
            BARN(1);
#pragma unroll
            for (int g = 0; g < 3; g++)
#pragma unroll
                for (int p = 0; p < 8; p++)
                    dmp[tid * 25 + g * 8 + p] = acc[hh * 3 + g][p];
            BARN(1);
            if (tid < 96) {
                int cgo = tid / 24, s = tid % 24;
                unsigned long long sum = dmp[(cgo * 64) * 25 + s];
#pragma unroll 8
                for (int q = 1; q < 64; q++)
                    ADD2(sum, dmp[(cgo * 64 + q) * 25 + s]);
                red_s[hh * 96 + cgo * 24 + s] = sum;
            }
        }
        BARN(1);

        if (tid < 128) {
            int cgc = jl_c >> 1, hh = jl_c & 1, p = b_c >> 1, lane = b_c & 1;
            const float* rf = (const float*)red_s;
            int base = (hh * 96 + cgc * 24) * 2 + p * 2 + lane;
            float ar = rf[base];
            float az = rf[base + 16];
            float an = rf[base + 32];

            float r = 1.f / (1.f + expf(-(gir + ar + bh0)));
            float z = 1.f / (1.f + expf(-(giz + az + bh1)));
            float n = tanhf(gin + r * (an + bh2));
            float hnew = (1.f - z) * n + z * hprev;

            rnn[((size_t)b_c * SDIM + t) * HDIM + col_c] = hnew;
            hT[(t & 1) * (HDIM * BDIM) + col_c * BDIM + b_c] = hnew;
        }

        // chip barrier (R4-style, GRU blocks only, replay-safe)
        BARN(1);
        if (tid == 0) {
            unsigned gen = g_gen;
            __threadfence();
            if (atomicAdd(&g_count, 1u) == NBLK - 1u) {
                g_count = 0;
                __threadfence();
                g_gen = gen + 1;
            } else {
                while (g_gen == gen) {}
                __threadfence();
            }
        }
        BARN(1);
    }
}

__global__ void __launch_bounds__(512, 1) gru_gi_fused(
    const float* __restrict__ x, const float* __restrict__ w_ih,
    const float* __restrict__ b_ih,
    const float* __restrict__ w_hh, const float* __restrict__ b_hh,
    float* __restrict__ gi, float* __restrict__ rnn, float* __restrict__ hT)
{
    extern __shared__ float sm[];
    const int bx = blockIdx.x;
    const int tidx = threadIdx.x;

    if (tidx < 256) {
        // lower half: gi worker everywhere (barrier 2, region A)
        gi_worker(x, w_ih, b_ih, gi, sm, 2, tidx);
    } else if (bx < NBLK) {
        // upper half of GRU blocks: the recurrence (barrier 1)
        gru_role(gi, w_hh, b_hh, rnn, hT, sm, tidx - 256, bx);
    } else {
        // upper half of extra blocks: second worker group (barrier 3, region B)
        gi_worker(x, w_ih, b_ih, gi, sm + GEMM_REGION, 3, tidx - 256);
    }
}

// ---------------------------------------------------------------------------
// hidden = rnn[:, S-1, :]; attn = ones.
// ---------------------------------------------------------------------------
__global__ void finalize_kernel(const float* __restrict__ rnn, float* __restrict__ out)
{
    const size_t OUT_ELEMS = (size_t)BDIM * SDIM * IDIM;
    int i = blockIdx.x * blockDim.x + threadIdx.x;
    if (i < BDIM * HDIM) {
        int b = i >> 10, h = i & 1023;
        out[OUT_ELEMS + i] = rnn[((size_t)b * SDIM + (SDIM - 1)) * HDIM + h];
    }
    if (i < BDIM * SDIM) {
        out[OUT_ELEMS + BDIM * HDIM + i] = 1.0f;
    }
}

extern "C" void kernel_launch(void* const* d_in, const int* in_sizes, int n_in,
                              void* d_out, int out_size)
{
    const float* x    = (const float*)d_in[0];
    // d_in[1..4] = attn MLP -> algebraically dead (softmax over size-1 axis == 1)
    const float* w_ih = (const float*)d_in[5];
    const float* w_hh = (const float*)d_in[6];
    const float* b_ih = (const float*)d_in[7];
    const float* b_hh = (const float*)d_in[8];
    const float* fc_w = (const float*)d_in[9];
    const float* fc_b = (const float*)d_in[10];
    float* out = (float*)d_out;

    float *gi = nullptr, *rnn = nullptr, *hT = nullptr;
    cudaGetSymbolAddress((void**)&gi, g_gi);
    cudaGetSymbolAddress((void**)&rnn, g_rnn);
    cudaGetSymbolAddress((void**)&hT, g_hT);

    const int smemB = SMEM_FLOATS * (int)sizeof(float);   // 215040 B
    static bool attr_done = false;
    if (!attr_done) {
        cudaFuncSetAttribute(gru_gi_fused, cudaFuncAttributeMaxDynamicSharedMemorySize, smemB);
        attr_done = true;
    }

    // reset the gi tile queue + band counters (stream-ordered)
    reset_queue_kernel<<<1, 32>>>();

    // fused: gi GEMM (worker groups) + persistent GRU, overlapped
    gru_gi_fused<<<NGRID, 512, smemB>>>(x, w_ih, b_ih, w_hh, b_hh, gi, rnn, hT);

    // output = rnn_out @ fc_w^T + fc_b   (M=32768, N=1024, K=1024)
    {
        dim3 grid(IDIM / 128, BDIM * SDIM / 128);
        sgemm_nt<<<grid, 256>>>(rnn, fc_w, fc_b, out, BDIM * SDIM, IDIM, HDIM);
    }

    finalize_kernel<<<192, 256>>>(rnn, out);
}

// round 16
// speedup vs baseline: 1.1436x; 1.1436x over previous
#include <cuda_runtime.h>
#include <math.h>

#define BDIM 16
#define SDIM 2048
#define IDIM 1024
#define HDIM 1024
#define NBLK 128   // GRU persistent blocks (1 per SM, 8 hidden cols each)

// Scratch (static __device__ — runtime allocation is forbidden)
__device__ float g_gi[(size_t)BDIM * SDIM * 3 * HDIM];   // [B,S,3H]
__device__ float g_rnn[(size_t)BDIM * SDIM * HDIM];      // [B,S,H]
__device__ float g_hT[2 * BDIM * HDIM];                  // h, double-buffered, [buf][b][k]

// grid barrier state (self-resetting across graph replays)
__device__ unsigned g_count = 0;
__device__ volatile unsigned g_gen = 0;

// ---------------------------------------------------------------------------
// f32x2 packed-math helpers (sm_100+)
// ---------------------------------------------------------------------------
__device__ __forceinline__ unsigned long long dup2(float x) {
    unsigned long long r;
    asm("mov.b64 %0, {%1, %1};" : "=l"(r) : "f"(x));
    return r;
}
__device__ __forceinline__ float2 unpack2(unsigned long long v) {
    float2 f;
    asm("mov.b64 {%0, %1}, %2;" : "=f"(f.x), "=f"(f.y) : "l"(v));
    return f;
}
#define FMA2(d, a, b) asm("fma.rn.f32x2 %0, %1, %2, %0;" : "+l"(d) : "l"(a), "l"(b))
#define ADD2(d, a)    asm("add.rn.f32x2 %0, %0, %1;"     : "+l"(d) : "l"(a))

// ---------------------------------------------------------------------------
// NT SGEMM (f32x2), BK=8, double-buffered smem + 8-reg prefetch (R12 exact).
// ---------------------------------------------------------------------------
__global__ void __launch_bounds__(256, 2) sgemm_nt(
    const float* __restrict__ A, const float* __restrict__ W,
    const float* __restrict__ bias, float* __restrict__ C,
    int M, int N, int K)
{
    __shared__ float As[2][8][128];
    __shared__ float Bs[2][8][128];

    const int tid = threadIdx.x;
    const int bm = blockIdx.y * 128;
    const int bn = blockIdx.x * 128;
    const int tx = tid & 15;
    const int ty = tid >> 4;
    const int lr = tid >> 1;
    const int hf = tid & 1;

    const float* Ap = A + (size_t)(bm + lr) * K + hf * 4;
    const float* Wp = W + (size_t)(bn + lr) * K + hf * 4;

    unsigned long long acc[8][4];
#pragma unroll
    for (int i = 0; i < 8; i++)
#pragma unroll
        for (int j = 0; j < 4; j++) acc[i][j] = 0ull;

    {
        float4 a0 = *(const float4*)(Ap);
        float4 w0 = *(const float4*)(Wp);
        As[0][hf * 4 + 0][lr] = a0.x; As[0][hf * 4 + 1][lr] = a0.y;
        As[0][hf * 4 + 2][lr] = a0.z; As[0][hf * 4 + 3][lr] = a0.w;
        Bs[0][hf * 4 + 0][lr] = w0.x; Bs[0][hf * 4 + 1][lr] = w0.y;
        Bs[0][hf * 4 + 2][lr] = w0.z; Bs[0][hf * 4 + 3][lr] = w0.w;
    }
    __syncthreads();

    const int NS = K / 8;
    for (int s = 0; s < NS; s++) {
        float4 an, wn;
        const bool more = (s + 1 < NS);
        if (more) {
            an = *(const float4*)(Ap + (s + 1) * 8);
            wn = *(const float4*)(Wp + (s + 1) * 8);
        }
        const int b = s & 1;
#pragma unroll
        for (int k = 0; k < 8; k++) {
            float a8[8];
            *(float4*)&a8[0] = *(const float4*)&As[b][k][ty * 8];
            *(float4*)&a8[4] = *(const float4*)&As[b][k][ty * 8 + 4];
            unsigned long long bp[4];
            {
                ulonglong2 t0 = *(const ulonglong2*)&Bs[b][k][tx * 8];
                ulonglong2 t1 = *(const ulonglong2*)&Bs[b][k][tx * 8 + 4];
                bp[0] = t0.x; bp[1] = t0.y; bp[2] = t1.x; bp[3] = t1.y;
            }
            unsigned long long ad[8];
#pragma unroll
            for (int i = 0; i < 8; i++) ad[i] = dup2(a8[i]);
#pragma unroll
            for (int i = 0; i < 8; i++)
#pragma unroll
                for (int j = 0; j < 4; j++)
                    FMA2(acc[i][j], ad[i], bp[j]);
        }
        if (more) {
            const int nb = b ^ 1;
            As[nb][hf * 4 + 0][lr] = an.x; As[nb][hf * 4 + 1][lr] = an.y;
            As[nb][hf * 4 + 2][lr] = an.z; As[nb][hf * 4 + 3][lr] = an.w;
            Bs[nb][hf * 4 + 0][lr] = wn.x; Bs[nb][hf * 4 + 1][lr] = wn.y;
            Bs[nb][hf * 4 + 2][lr] = wn.z; Bs[nb][hf * 4 + 3][lr] = wn.w;
        }
        __syncthreads();
    }

#pragma unroll
    for (int i = 0; i < 8; i++) {
        size_t row = (size_t)(bm + ty * 8 + i);
#pragma unroll
        for (int j = 0; j < 4; j++) {
            float2 f = unpack2(acc[i][j]);
            int n = bn + tx * 8 + 2 * j;
            float2 v;
            v.x = f.x + bias[n];
            v.y = f.y + bias[n + 1];
            *(float2*)&C[row * N + n] = v;
        }
    }
}

// ---------------------------------------------------------------------------
// Persistent GRU v3: k-packed f32x2 accumulation.
// 128 blocks x 256 threads; block owns 8 hidden cols.
// Thread (kh = tid>>7, b = (tid>>3)&15, j = tid&7): 3 gates x 512 k.
// w_s: 24 rows (g*8+j) stride 1044 (conflict-free LDS.128 across 8 j).
// h_s: [q=k/4][b][4] stride 68 per q-row (phase-optimal LDS.128 across b).
// Reduction: intra-thread ADD2 -> 3KB dump by kh=1 -> partner ADD2 -> done.
// ---------------------------------------------------------------------------
__device__ __forceinline__ void gsync() {
    __syncthreads();
    if (threadIdx.x == 0) {
        unsigned gen = g_gen;
        __threadfence();
        if (atomicAdd(&g_count, 1u) == NBLK - 1u) {
            g_count = 0;
            __threadfence();
            g_gen = gen + 1;
        } else {
            while (g_gen == gen) {}
            __threadfence();
        }
    }
    __syncthreads();
}

#define WSTR 1044                         // w_s row stride (floats)
#define SM_W   (24 * WSTR)                // 25056 floats
#define SM_H   (256 * 68)                 // 17408 floats
#define SM_RED 384                        // ull entries (kh=1 partials)

__global__ void __launch_bounds__(256, 1) gru_persistent(
    const float* __restrict__ gi, const float* __restrict__ w_hh,
    const float* __restrict__ b_hh, float* __restrict__ rnn,
    float* __restrict__ hT)
{
    extern __shared__ float sm[];
    float* w_s = sm;
    float* h_s = sm + SM_W;
    unsigned long long* red_s = (unsigned long long*)(sm + SM_W + SM_H);

    const int tid = threadIdx.x;
    const int bx = blockIdx.x;
    const int kh = tid >> 7;          // k half
    const int bb = (tid >> 3) & 15;   // batch
    const int jj = tid & 7;           // local col
    const int col = bx * 8 + jj;

    // --- load own w_hh rows into smem (once), padded stride ---
    for (int idx = tid; idx < 24 * 256; idx += 256) {
        int lr = idx >> 8;
        int k4 = idx & 255;
        int g = lr >> 3, jl = lr & 7;
        float4 v = *(const float4*)(w_hh + ((size_t)(g * 1024 + bx * 8 + jl)) * 1024 + k4 * 4);
        *(float4*)(w_s + lr * WSTR + k4 * 4) = v;
    }

    float bh0 = 0.f, bh1 = 0.f, bh2 = 0.f;
    if (tid < 128) {
        bh0 = b_hh[col];
        bh1 = b_hh[1024 + col];
        bh2 = b_hh[2048 + col];
    }

    const float* wrow0 = w_s + (0 * 8 + jj) * WSTR + kh * 512;
    const float* wrow1 = w_s + (1 * 8 + jj) * WSTR + kh * 512;
    const float* wrow2 = w_s + (2 * 8 + jj) * WSTR + kh * 512;
    const float* hbase = h_s + kh * 128 * 68 + bb * 4;

    __syncthreads();

    for (int t = 0; t < SDIM; t++) {
        // --- prefetch gi (hidden under staging+mainloop) ---
        float gir = 0.f, giz = 0.f, gin = 0.f;
        if (tid < 128) {
            const size_t gb = ((size_t)bb * SDIM + t) * 3072 + col;
            gir = __ldg(gi + gb);
            giz = __ldg(gi + gb + 1024);
            gin = __ldg(gi + gb + 2048);
        }

        // --- stage h_{t-1}: hT[b][k] -> h_s[q][b][4] ---
        if (t == 0) {
            float4 z4 = make_float4(0.f, 0.f, 0.f, 0.f);
            for (int r = tid; r < SM_H / 4; r += 256)
                ((float4*)h_s)[r] = z4;
        } else {
            const float* src = hT + ((t - 1) & 1) * (BDIM * HDIM);
            for (int r = tid; r < 4096; r += 256) {
                int b = r >> 8, q = r & 255;
                float4 v = *(const float4*)(src + b * 1024 + q * 4);
                *(float4*)(h_s + q * 68 + b * 4) = v;
            }
        }
        __syncthreads();

        float hprev = 0.f;
        if (tid < 128) hprev = h_s[(col >> 2) * 68 + bb * 4 + (col & 3)];

        // --- mainloop: 128 iters x (4 LDS.128 + 6 FMA2) ---
        unsigned long long a0l = 0ull, a0h = 0ull;
        unsigned long long a1l = 0ull, a1h = 0ull;
        unsigned long long a2l = 0ull, a2h = 0ull;
#pragma unroll 4
        for (int i = 0; i < 128; i++) {
            ulonglong2 hv = *(const ulonglong2*)(hbase + i * 68);
            ulonglong2 w0 = *(const ulonglong2*)(wrow0 + i * 4);
            FMA2(a0l, w0.x, hv.x);
            FMA2(a0h, w0.y, hv.y);
            ulonglong2 w1 = *(const ulonglong2*)(wrow1 + i * 4);
            FMA2(a1l, w1.x, hv.x);
            FMA2(a1h, w1.y, hv.y);
            ulonglong2 w2 = *(const ulonglong2*)(wrow2 + i * 4);
            FMA2(a2l, w2.x, hv.x);
            FMA2(a2h, w2.y, hv.y);
        }
        ADD2(a0l, a0h);
        ADD2(a1l, a1h);
        ADD2(a2l, a2h);

        // --- reduction: kh=1 dumps 3 ull, kh=0 combines ---
        if (kh) {
            unsigned long long* rp = red_s + (tid - 128) * 3;
            rp[0] = a0l; rp[1] = a1l; rp[2] = a2l;
        }
        __syncthreads();

        if (tid < 128) {
            const unsigned long long* rp = red_s + tid * 3;
            ADD2(a0l, rp[0]);
            ADD2(a1l, rp[1]);
            ADD2(a2l, rp[2]);
            float2 f0 = unpack2(a0l);
            float2 f1 = unpack2(a1l);
            float2 f2 = unpack2(a2l);
            float ar = f0.x + f0.y;
            float az = f1.x + f1.y;
            float an = f2.x + f2.y;

            float r = 1.f / (1.f + expf(-(gir + ar + bh0)));
            float z = 1.f / (1.f + expf(-(giz + az + bh1)));
            float n = tanhf(gin + r * (an + bh2));
            float hnew = (1.f - z) * n + z * hprev;

            rnn[((size_t)bb * SDIM + t) * HDIM + col] = hnew;
            hT[(t & 1) * (BDIM * HDIM) + bb * 1024 + col] = hnew;
        }

        gsync();   // h_T[t] visible chip-wide before anyone stages step t+1
    }
}

// ---------------------------------------------------------------------------
// hidden = rnn[:, S-1, :]; attn = ones (softmax over a size-1 axis).
// d_out layout: [output B*S*I][hidden B*H][attn B*S]
// ---------------------------------------------------------------------------
__global__ void finalize_kernel(const float* __restrict__ rnn, float* __restrict__ out)
{
    const size_t OUT_ELEMS = (size_t)BDIM * SDIM * IDIM;
    int i = blockIdx.x * blockDim.x + threadIdx.x;
    if (i < BDIM * HDIM) {
        int b = i >> 10, h = i & 1023;
        out[OUT_ELEMS + i] = rnn[((size_t)b * SDIM + (SDIM - 1)) * HDIM + h];
    }
    if (i < BDIM * SDIM) {
        out[OUT_ELEMS + BDIM * HDIM + i] = 1.0f;
    }
}

extern "C" void kernel_launch(void* const* d_in, const int* in_sizes, int n_in,
                              void* d_out, int out_size)
{
    const float* x    = (const float*)d_in[0];
    // d_in[1..4] = attn MLP -> algebraically dead (softmax over size-1 axis == 1)
    const float* w_ih = (const float*)d_in[5];
    const float* w_hh = (const float*)d_in[6];
    const float* b_ih = (const float*)d_in[7];
    const float* b_hh = (const float*)d_in[8];
    const float* fc_w = (const float*)d_in[9];
    const float* fc_b = (const float*)d_in[10];
    float* out = (float*)d_out;

    float *gi = nullptr, *rnn = nullptr, *hT = nullptr;
    cudaGetSymbolAddress((void**)&gi, g_gi);
    cudaGetSymbolAddress((void**)&rnn, g_rnn);
    cudaGetSymbolAddress((void**)&hT, g_hT);

    const int smemB = (SM_W + SM_H) * (int)sizeof(float) + SM_RED * (int)sizeof(unsigned long long);
    static bool attr_done = false;
    if (!attr_done) {
        cudaFuncSetAttribute(gru_persistent, cudaFuncAttributeMaxDynamicSharedMemorySize, smemB);
        attr_done = true;
    }

    // gi = x @ w_ih^T + b_ih   (M=32768, N=3072, K=1024)
    {
        dim3 grid(3 * HDIM / 128, BDIM * SDIM / 128);
        sgemm_nt<<<grid, 256>>>(x, w_ih, b_ih, gi, BDIM * SDIM, 3 * HDIM, IDIM);
    }

    // GRU: one persistent kernel, 2048 steps, software grid barrier
    gru_persistent<<<NBLK, 256, smemB>>>(gi, w_hh, b_hh, rnn, hT);

    // output = rnn_out @ fc_w^T + fc_b   (M=32768, N=1024, K=1024)
    {
        dim3 grid(IDIM / 128, BDIM * SDIM / 128);
        sgemm_nt<<<grid, 256>>>(rnn, fc_w, fc_b, out, BDIM * SDIM, IDIM, HDIM);
    }

    finalize_kernel<<<192, 256>>>(rnn, out);
}

// round 17
// speedup vs baseline: 1.5759x; 1.3781x over previous
#include <cuda_runtime.h>
#include <math.h>

#define BDIM 16
#define SDIM 2048
#define IDIM 1024
#define HDIM 1024
#define NBLK 128   // GRU persistent blocks (1 per SM, 8 hidden cols each)

// Scratch (static __device__ — runtime allocation is forbidden)
__device__ float g_gi[(size_t)BDIM * SDIM * 3 * HDIM];   // [B,S,3H]
__device__ float g_rnn[(size_t)BDIM * SDIM * HDIM];      // [B,S,H]
__device__ float g_hT[2 * HDIM * BDIM];                  // transposed h, double-buffered [buf][k][b]

// grid barrier state (self-resetting across graph replays)
__device__ unsigned g_count = 0;
__device__ volatile unsigned g_gen = 0;

// ---------------------------------------------------------------------------
// f32x2 packed-math helpers (sm_100+)
// ---------------------------------------------------------------------------
__device__ __forceinline__ unsigned long long dup2(float x) {
    unsigned long long r;
    asm("mov.b64 %0, {%1, %1};" : "=l"(r) : "f"(x));
    return r;
}
__device__ __forceinline__ float2 unpack2(unsigned long long v) {
    float2 f;
    asm("mov.b64 {%0, %1}, %2;" : "=f"(f.x), "=f"(f.y) : "l"(v));
    return f;
}
#define FMA2(d, a, b) asm("fma.rn.f32x2 %0, %1, %2, %0;" : "+l"(d) : "l"(a), "l"(b))
#define ADD2(d, a)    asm("add.rn.f32x2 %0, %0, %1;"     : "+l"(d) : "l"(a))

// ---------------------------------------------------------------------------
// NT SGEMM (f32x2), BK=8, double-buffered smem + 8-reg prefetch (R12 exact).
// ---------------------------------------------------------------------------
__global__ void __launch_bounds__(256, 2) sgemm_nt(
    const float* __restrict__ A, const float* __restrict__ W,
    const float* __restrict__ bias, float* __restrict__ C,
    int M, int N, int K)
{
    __shared__ float As[2][8][128];
    __shared__ float Bs[2][8][128];

    const int tid = threadIdx.x;
    const int bm = blockIdx.y * 128;
    const int bn = blockIdx.x * 128;
    const int tx = tid & 15;
    const int ty = tid >> 4;
    const int lr = tid >> 1;
    const int hf = tid & 1;

    const float* Ap = A + (size_t)(bm + lr) * K + hf * 4;
    const float* Wp = W + (size_t)(bn + lr) * K + hf * 4;

    unsigned long long acc[8][4];
#pragma unroll
    for (int i = 0; i < 8; i++)
#pragma unroll
        for (int j = 0; j < 4; j++) acc[i][j] = 0ull;

    {
        float4 a0 = *(const float4*)(Ap);
        float4 w0 = *(const float4*)(Wp);
        As[0][hf * 4 + 0][lr] = a0.x; As[0][hf * 4 + 1][lr] = a0.y;
        As[0][hf * 4 + 2][lr] = a0.z; As[0][hf * 4 + 3][lr] = a0.w;
        Bs[0][hf * 4 + 0][lr] = w0.x; Bs[0][hf * 4 + 1][lr] = w0.y;
        Bs[0][hf * 4 + 2][lr] = w0.z; Bs[0][hf * 4 + 3][lr] = w0.w;
    }
    __syncthreads();

    const int NS = K / 8;
    for (int s = 0; s < NS; s++) {
        float4 an, wn;
        const bool more = (s + 1 < NS);
        if (more) {
            an = *(const float4*)(Ap + (s + 1) * 8);
            wn = *(const float4*)(Wp + (s + 1) * 8);
        }
        const int b = s & 1;
#pragma unroll
        for (int k = 0; k < 8; k++) {
            float a8[8];
            *(float4*)&a8[0] = *(const float4*)&As[b][k][ty * 8];
            *(float4*)&a8[4] = *(const float4*)&As[b][k][ty * 8 + 4];
            unsigned long long bp[4];
            {
                ulonglong2 t0 = *(const ulonglong2*)&Bs[b][k][tx * 8];
                ulonglong2 t1 = *(const ulonglong2*)&Bs[b][k][tx * 8 + 4];
                bp[0] = t0.x; bp[1] = t0.y; bp[2] = t1.x; bp[3] = t1.y;
            }
            unsigned long long ad[8];
#pragma unroll
            for (int i = 0; i < 8; i++) ad[i] = dup2(a8[i]);
#pragma unroll
            for (int i = 0; i < 8; i++)
#pragma unroll
                for (int j = 0; j < 4; j++)
                    FMA2(acc[i][j], ad[i], bp[j]);
        }
        if (more) {
            const int nb = b ^ 1;
            As[nb][hf * 4 + 0][lr] = an.x; As[nb][hf * 4 + 1][lr] = an.y;
            As[nb][hf * 4 + 2][lr] = an.z; As[nb][hf * 4 + 3][lr] = an.w;
            Bs[nb][hf * 4 + 0][lr] = wn.x; Bs[nb][hf * 4 + 1][lr] = wn.y;
            Bs[nb][hf * 4 + 2][lr] = wn.z; Bs[nb][hf * 4 + 3][lr] = wn.w;
        }
        __syncthreads();
    }

#pragma unroll
    for (int i = 0; i < 8; i++) {
        size_t row = (size_t)(bm + ty * 8 + i);
#pragma unroll
        for (int j = 0; j < 4; j++) {
            float2 f = unpack2(acc[i][j]);
            int n = bn + tx * 8 + 2 * j;
            float2 v;
            v.x = f.x + bias[n];
            v.y = f.y + bias[n + 1];
            *(float2*)&C[row * N + n] = v;
        }
    }
}

// ---------------------------------------------------------------------------
// Persistent GRU — R12 structure exactly; ONLY change: reduction uses two
// independent 32-long ADD2 chains (halves the serial RAW chain).
// 128 blocks x 256 threads; block owns 8 hidden cols.
// ---------------------------------------------------------------------------
__device__ __forceinline__ void gsync() {
    __syncthreads();
    if (threadIdx.x == 0) {
        unsigned gen = g_gen;
        __threadfence();
        if (atomicAdd(&g_count, 1u) == NBLK - 1u) {
            g_count = 0;
            __threadfence();
            g_gen = gen + 1;
        } else {
            while (g_gen == gen) {}
            __threadfence();
        }
    }
    __syncthreads();
}

#define HROW 20            // floats per h_s row (16 used + 4 pad -> conflict-free LDS.128)
#define SM_W   (24 * 1024)                 // floats
#define SM_H   (1024 * HROW)               // floats
#define SM_RED 192                         // ull (f32x2) entries

__global__ void __launch_bounds__(256, 1) gru_persistent(
    const float* __restrict__ gi, const float* __restrict__ w_hh,
    const float* __restrict__ b_hh, float* __restrict__ rnn,
    float* __restrict__ hT)
{
    extern __shared__ float sm[];
    float* w_s = sm;
    float* h_s = sm + SM_W;
    unsigned long long* red_s = (unsigned long long*)(sm + SM_W + SM_H);

    const int tid = threadIdx.x;
    const int bx = blockIdx.x;
    const int cg = tid >> 6;      // 0..3 column group
    const int ks = tid & 63;      // k slice

    // --- load own w_hh rows into smem (once) ---
    for (int idx = tid; idx < 24 * 256; idx += 256) {
        int lr = idx >> 8;
        int k4 = idx & 255;
        int g = lr >> 3, jl = lr & 7;
        float4 v = *(const float4*)(w_hh + ((size_t)(g * 1024 + bx * 8 + jl)) * 1024 + k4 * 4);
        *(float4*)(w_s + lr * 1024 + k4 * 4) = v;
    }

    // combine-thread constants
    const int jl_c = tid >> 4, b_c = tid & 15;
    const int col_c = bx * 8 + jl_c;
    float bh0 = 0.f, bh1 = 0.f, bh2 = 0.f;
    if (tid < 128) {
        bh0 = b_hh[col_c];
        bh1 = b_hh[1024 + col_c];
        bh2 = b_hh[2048 + col_c];
    }

    // per-thread w pointers (invariant across steps): c = jsub*3 + g
    const int j0 = cg * 2;
    const float* wc[6];
#pragma unroll
    for (int jsub = 0; jsub < 2; jsub++)
#pragma unroll
        for (int g = 0; g < 3; g++)
            wc[jsub * 3 + g] = w_s + (g * 8 + j0 + jsub) * 1024 + ks;

    __syncthreads();

    for (int t = 0; t < SDIM; t++) {
        // --- stage h_{t-1} into h_s[k][b] ---
        if (t == 0) {
            float4 z4 = make_float4(0.f, 0.f, 0.f, 0.f);
            for (int r = tid; r < SM_H / 4; r += 256)
                ((float4*)h_s)[r] = z4;
        } else {
            const size_t hoff = (size_t)((t - 1) & 1) * (HDIM * BDIM);
            for (int r = tid; r < 4096; r += 256) {
                float4 v = *(const float4*)(hT + hoff + r * 4);
                int k = r >> 2, b4 = r & 3;
                *(float4*)(h_s + k * HROW + b4 * 4) = v;
            }
        }
        __syncthreads();

        // --- prefetch gi + hprev (hidden under the mainloop) ---
        float gir = 0.f, giz = 0.f, gin = 0.f, hprev = 0.f;
        if (tid < 128) {
            const size_t gb = ((size_t)b_c * SDIM + t) * 3072 + col_c;
            gir = __ldg(gi + gb);
            giz = __ldg(gi + gb + 1024);
            gin = __ldg(gi + gb + 2048);
            hprev = h_s[col_c * HROW + b_c];
        }

        // --- mainloop: 6 cols x 8 f32x2 x 16 k-iters ---
        unsigned long long acc[6][8];
#pragma unroll
        for (int c = 0; c < 6; c++)
#pragma unroll
            for (int p = 0; p < 8; p++) acc[c][p] = 0ull;

#pragma unroll 4
        for (int i = 0; i < 16; i++) {
            const int k = ks + (i << 6);
            const float* hrow = h_s + k * HROW;
            unsigned long long hp[8];
            {
                ulonglong2 u0 = *(const ulonglong2*)(hrow);
                ulonglong2 u1 = *(const ulonglong2*)(hrow + 4);
                ulonglong2 u2 = *(const ulonglong2*)(hrow + 8);
                ulonglong2 u3 = *(const ulonglong2*)(hrow + 12);
                hp[0] = u0.x; hp[1] = u0.y; hp[2] = u1.x; hp[3] = u1.y;
                hp[4] = u2.x; hp[5] = u2.y; hp[6] = u3.x; hp[7] = u3.y;
            }
#pragma unroll
            for (int c = 0; c < 6; c++) {
                unsigned long long wd = dup2(wc[c][i << 6]);
#pragma unroll
                for (int p = 0; p < 8; p++) FMA2(acc[c][p], wd, hp[p]);
            }
        }

        // --- 64-way k reduction in two halves (dump reuses h_s) ---
        // ONLY CHANGE vs R12: the 64-sum runs as two independent 32-chains.
        unsigned long long* dmp = (unsigned long long*)h_s;
#pragma unroll
        for (int hh = 0; hh < 2; hh++) {
            __syncthreads();   // h_s / previous dump fully consumed
#pragma unroll
            for (int g = 0; g < 3; g++)
#pragma unroll
                for (int p = 0; p < 8; p++)
                    dmp[tid * 25 + g * 8 + p] = acc[hh * 3 + g][p];
            __syncthreads();
            if (tid < 96) {
                int cgo = tid / 24, s = tid % 24;
                const unsigned long long* base = dmp + (size_t)(cgo * 64) * 25 + s;
                unsigned long long s0 = base[0];
                unsigned long long s1 = base[32 * 25];
#pragma unroll 8
                for (int q = 1; q < 32; q++) {
                    ADD2(s0, base[q * 25]);
                    ADD2(s1, base[(32 + q) * 25]);
                }
                ADD2(s0, s1);
                red_s[hh * 96 + cgo * 24 + s] = s0;
            }
        }
        __syncthreads();

        // --- combine + activations + write ---
        if (tid < 128) {
            int cgc = jl_c >> 1, hh = jl_c & 1, p = b_c >> 1, lane = b_c & 1;
            const float* rf = (const float*)red_s;
            int base = (hh * 96 + cgc * 24) * 2 + p * 2 + lane;
            float ar = rf[base];
            float az = rf[base + 16];   // (g=1)*8*2
            float an = rf[base + 32];   // (g=2)*8*2

            float r = 1.f / (1.f + expf(-(gir + ar + bh0)));
            float z = 1.f / (1.f + expf(-(giz + az + bh1)));
            float n = tanhf(gin + r * (an + bh2));
            float hnew = (1.f - z) * n + z * hprev;

            rnn[((size_t)b_c * SDIM + t) * HDIM + col_c] = hnew;
            hT[(t & 1) * (HDIM * BDIM) + col_c * BDIM + b_c] = hnew;
        }

        gsync();   // h_T[t] visible chip-wide before anyone stages step t+1
    }
}

// ---------------------------------------------------------------------------
// hidden = rnn[:, S-1, :]; attn = ones (softmax over a size-1 axis).
// d_out layout: [output B*S*I][hidden B*H][attn B*S]
// ---------------------------------------------------------------------------
__global__ void finalize_kernel(const float* __restrict__ rnn, float* __restrict__ out)
{
    const size_t OUT_ELEMS = (size_t)BDIM * SDIM * IDIM;
    int i = blockIdx.x * blockDim.x + threadIdx.x;
    if (i < BDIM * HDIM) {
        int b = i >> 10, h = i & 1023;
        out[OUT_ELEMS + i] = rnn[((size_t)b * SDIM + (SDIM - 1)) * HDIM + h];
    }
    if (i < BDIM * SDIM) {
        out[OUT_ELEMS + BDIM * HDIM + i] = 1.0f;
    }
}

extern "C" void kernel_launch(void* const* d_in, const int* in_sizes, int n_in,
                              void* d_out, int out_size)
{
    const float* x    = (const float*)d_in[0];
    // d_in[1..4] = attn MLP -> algebraically dead (softmax over size-1 axis == 1)
    const float* w_ih = (const float*)d_in[5];
    const float* w_hh = (const float*)d_in[6];
    const float* b_ih = (const float*)d_in[7];
    const float* b_hh = (const float*)d_in[8];
    const float* fc_w = (const float*)d_in[9];
    const float* fc_b = (const float*)d_in[10];
    float* out = (float*)d_out;

    float *gi = nullptr, *rnn = nullptr, *hT = nullptr;
    cudaGetSymbolAddress((void**)&gi, g_gi);
    cudaGetSymbolAddress((void**)&rnn, g_rnn);
    cudaGetSymbolAddress((void**)&hT, g_hT);

    const int smemB = (SM_W + SM_H) * (int)sizeof(float) + SM_RED * (int)sizeof(unsigned long long);
    static bool attr_done = false;
    if (!attr_done) {
        cudaFuncSetAttribute(gru_persistent, cudaFuncAttributeMaxDynamicSharedMemorySize, smemB);
        attr_done = true;
    }

    // gi = x @ w_ih^T + b_ih   (M=32768, N=3072, K=1024)
    {
        dim3 grid(3 * HDIM / 128, BDIM * SDIM / 128);
        sgemm_nt<<<grid, 256>>>(x, w_ih, b_ih, gi, BDIM * SDIM, 3 * HDIM, IDIM);
    }

    // GRU: one persistent kernel, 2048 steps, software grid barrier
    gru_persistent<<<NBLK, 256, smemB>>>(gi, w_hh, b_hh, rnn, hT);

    // output = rnn_out @ fc_w^T + fc_b   (M=32768, N=1024, K=1024)
    {
        dim3 grid(IDIM / 128, BDIM * SDIM / 128);
        sgemm_nt<<<grid, 256>>>(rnn, fc_w, fc_b, out, BDIM * SDIM, IDIM, HDIM);
    }

    finalize_kernel<<<192, 256>>>(rnn, out);
}